// round 2
// baseline (speedup 1.0000x reference)
#include <cuda_runtime.h>
#include <math.h>

#define H 1024
#define V 50257
#define S 4096
#define G3H 3072   // 3*H

// ---- scratch (allocation-free rule: __device__ globals) ----
__device__ float g_gi[G3H];
__device__ float g_gh[G3H];
__device__ float g_hnew[H];   // aligned copy of h_new for fast dot products
__device__ float g_ctx[H];    // aligned context accumulator

__device__ __forceinline__ float warp_sum(float v) {
#pragma unroll
    for (int o = 16; o; o >>= 1) v += __shfl_down_sync(0xffffffffu, v, o);
    return v;
}

__device__ __forceinline__ float sigmoidf_(float x) {
    return 1.0f / (1.0f + expf(-x));
}

// ============================================================================
// 1) gi = w_ih @ [emb; last_context] + b_ih   (rows 0..3071, len 2048)
//    gh = w_hh @ h                     + b_hh (rows 0..3071, len 1024)
//    One warp per row. 6144 warp-tasks.
// ============================================================================
__global__ void gates_kernel(const int* __restrict__ word,
                             const float* __restrict__ last_context,
                             const float* __restrict__ last_hidden,
                             const float* __restrict__ emb_tab,
                             const float* __restrict__ w_ih,
                             const float* __restrict__ w_hh,
                             const float* __restrict__ b_ih,
                             const float* __restrict__ b_hh) {
    int warp = (blockIdx.x * blockDim.x + threadIdx.x) >> 5;
    int lane = threadIdx.x & 31;

    if (warp < G3H) {
        // gi row: dot over 2048 = 512 float4
        const float4* wr   = (const float4*)(w_ih + (size_t)warp * (2 * H));
        const float4* embr = (const float4*)(emb_tab + (size_t)word[0] * H);
        const float4* lc4  = (const float4*)last_context;
        float acc = 0.f;
#pragma unroll
        for (int k = 0; k < 16; k++) {
            int j = lane + k * 32;               // 0..511
            float4 w4 = wr[j];
            float4 x4 = (j < 256) ? embr[j] : lc4[j - 256];
            acc += w4.x * x4.x + w4.y * x4.y + w4.z * x4.z + w4.w * x4.w;
        }
        acc = warp_sum(acc);
        if (lane == 0) g_gi[warp] = acc + b_ih[warp];
    } else if (warp < 2 * G3H) {
        int r = warp - G3H;
        const float4* wr = (const float4*)(w_hh + (size_t)r * H);
        const float4* h4 = (const float4*)last_hidden;   // (1,1,H) contiguous
        float acc = 0.f;
#pragma unroll
        for (int k = 0; k < 8; k++) {
            int j = lane + k * 32;               // 0..255
            float4 w4 = wr[j];
            float4 x4 = h4[j];
            acc += w4.x * x4.x + w4.y * x4.y + w4.z * x4.z + w4.w * x4.w;
        }
        acc = warp_sum(acc);
        if (lane == 0) g_gh[r] = acc + b_hh[r];
    }
}

// ============================================================================
// 2) GRU combine -> h_new  (1 block, 1024 threads)
// ============================================================================
__global__ void gru_kernel(const float* __restrict__ last_hidden,
                           float* __restrict__ out) {
    int d = threadIdx.x;
    float r = sigmoidf_(g_gi[d]       + g_gh[d]);
    float z = sigmoidf_(g_gi[d + H]   + g_gh[d + H]);
    float n = tanhf    (g_gi[d + 2*H] + r * g_gh[d + 2*H]);
    float h = last_hidden[d];
    float hn = (1.0f - z) * n + z * h;
    g_hnew[d] = hn;
    out[V + H + d] = hn;     // h_new output slot
}

// ============================================================================
// 3) scores[s] = enc[s,:] . h_new   (warp per row, 4096 rows)
//    raw scores written into the attn output slot (softmaxed in place later)
// ============================================================================
__global__ void scores_kernel(const float* __restrict__ enc,
                              float* __restrict__ scores) {
    int warp = blockIdx.x * (blockDim.x >> 5) + (threadIdx.x >> 5);
    int lane = threadIdx.x & 31;
    if (warp >= S) return;
    const float4* e4 = (const float4*)(enc + (size_t)warp * H);
    const float4* h4 = (const float4*)g_hnew;
    float acc = 0.f;
#pragma unroll
    for (int k = 0; k < 8; k++) {
        int j = lane + k * 32;
        float4 a = e4[j], b = h4[j];
        acc += a.x * b.x + a.y * b.y + a.z * b.z + a.w * b.w;
    }
    acc = warp_sum(acc);
    if (lane == 0) scores[warp] = acc;
}

// ============================================================================
// 4) softmax over S=4096, in place (1 block, 1024 threads). Also zero g_ctx.
// ============================================================================
__global__ void softmax_kernel(float* __restrict__ attn) {
    __shared__ float red[32];
    int tid = threadIdx.x;
    g_ctx[tid] = 0.0f;   // zero the context accumulator for this run

    float v[4];
#pragma unroll
    for (int k = 0; k < 4; k++) v[k] = attn[tid + k * 1024];

    // block max
    float m = fmaxf(fmaxf(v[0], v[1]), fmaxf(v[2], v[3]));
#pragma unroll
    for (int o = 16; o; o >>= 1) m = fmaxf(m, __shfl_down_sync(0xffffffffu, m, o));
    if ((tid & 31) == 0) red[tid >> 5] = m;
    __syncthreads();
    if (tid < 32) {
        float t = red[tid];
#pragma unroll
        for (int o = 16; o; o >>= 1) t = fmaxf(t, __shfl_down_sync(0xffffffffu, t, o));
        if (tid == 0) red[0] = t;
    }
    __syncthreads();
    float M = red[0];
    __syncthreads();

    // block sum of exp
    float s = 0.f;
#pragma unroll
    for (int k = 0; k < 4; k++) { v[k] = expf(v[k] - M); s += v[k]; }
    s = warp_sum(s);
    if ((tid & 31) == 0) red[tid >> 5] = s;
    __syncthreads();
    if (tid < 32) {
        float t = red[tid];
        t = warp_sum(t);
        if (tid == 0) red[0] = t;
    }
    __syncthreads();
    float inv = 1.0f / red[0];
#pragma unroll
    for (int k = 0; k < 4; k++) attn[tid + k * 1024] = v[k] * inv;
}

// ============================================================================
// 5) context[d] = sum_s attn[s] * enc[s,d]
//    grid (H/128, S/128), 128 threads; partial sums -> atomicAdd into g_ctx
// ============================================================================
__global__ void context_kernel(const float* __restrict__ enc,
                               const float* __restrict__ attn) {
    __shared__ float a_sh[128];
    int s0 = blockIdx.y * 128;
    int d  = blockIdx.x * 128 + threadIdx.x;
    a_sh[threadIdx.x] = attn[s0 + threadIdx.x];
    __syncthreads();
    float acc = 0.f;
#pragma unroll 4
    for (int i = 0; i < 128; i++)
        acc += a_sh[i] * enc[(size_t)(s0 + i) * H + d];
    atomicAdd(&g_ctx[d], acc);
}

// ============================================================================
// 6) logits[v] = out_w[v,:] . [h_new; context] + out_b[v]
//    THE big kernel: 412 MB of out_w. Warp per row, x in shared.
// ============================================================================
__global__ void logits_kernel(const float* __restrict__ out_w,
                              const float* __restrict__ out_b,
                              float* __restrict__ logits) {
    __shared__ float4 x4[512];           // [h_new(1024); context(1024)]
    float* xs = (float*)x4;
    for (int i = threadIdx.x; i < H; i += blockDim.x) {
        xs[i]     = g_hnew[i];
        xs[H + i] = g_ctx[i];
    }
    __syncthreads();

    int row  = blockIdx.x * (blockDim.x >> 5) + (threadIdx.x >> 5);
    int lane = threadIdx.x & 31;
    if (row >= V) return;

    const float4* wr = (const float4*)(out_w + (size_t)row * (2 * H));
    float acc = 0.f;
#pragma unroll
    for (int k = 0; k < 16; k++) {
        int j = lane + k * 32;           // 0..511
        float4 w4 = wr[j];
        float4 v4 = x4[j];
        acc += w4.x * v4.x + w4.y * v4.y + w4.z * v4.z + w4.w * v4.w;
    }
    acc = warp_sum(acc);
    if (lane == 0) logits[row] = acc + out_b[row];
}

// ============================================================================
// 7) log_softmax over V in place + copy context into d_out (1 block, 1024 thr)
// ============================================================================
__global__ void lsm_kernel(float* __restrict__ out) {
    __shared__ float red[32];
    int tid = threadIdx.x;

    // pass 1: max
    float m = -1e30f;
    for (int i = tid; i < V; i += 1024) m = fmaxf(m, out[i]);
#pragma unroll
    for (int o = 16; o; o >>= 1) m = fmaxf(m, __shfl_down_sync(0xffffffffu, m, o));
    if ((tid & 31) == 0) red[tid >> 5] = m;
    __syncthreads();
    if (tid < 32) {
        float t = red[tid];
#pragma unroll
        for (int o = 16; o; o >>= 1) t = fmaxf(t, __shfl_down_sync(0xffffffffu, t, o));
        if (tid == 0) red[0] = t;
    }
    __syncthreads();
    float M = red[0];
    __syncthreads();

    // pass 2: sum exp
    float s = 0.f;
    for (int i = tid; i < V; i += 1024) s += expf(out[i] - M);
    s = warp_sum(s);
    if ((tid & 31) == 0) red[tid >> 5] = s;
    __syncthreads();
    if (tid < 32) {
        float t = red[tid];
        t = warp_sum(t);
        if (tid == 0) red[0] = t;
    }
    __syncthreads();
    float lse = M + logf(red[0]);

    // pass 3: rewrite logits -> log-probs (each thread touches only its own indices)
    for (int i = tid; i < V; i += 1024) out[i] = out[i] - lse;

    // finalize: context output slot
    out[V + tid] = g_ctx[tid];
}

// ============================================================================
extern "C" void kernel_launch(void* const* d_in, const int* in_sizes, int n_in,
                              void* d_out, int out_size) {
    const int*   word  = (const int*)  d_in[0];
    const float* lc    = (const float*)d_in[1];
    const float* lh    = (const float*)d_in[2];
    const float* enc   = (const float*)d_in[3];
    const float* emb   = (const float*)d_in[4];
    const float* w_ih  = (const float*)d_in[5];
    const float* w_hh  = (const float*)d_in[6];
    const float* b_ih  = (const float*)d_in[7];
    const float* b_hh  = (const float*)d_in[8];
    const float* out_w = (const float*)d_in[9];
    const float* out_b = (const float*)d_in[10];
    float* out = (float*)d_out;

    float* attn_slot = out + V + 2 * H;   // raw scores -> softmax in place

    // 1) gates: 6144 warp-rows, 8 warps/block -> 768 blocks
    gates_kernel<<<768, 256>>>(word, lc, lh, emb, w_ih, w_hh, b_ih, b_hh);
    // 2) GRU combine
    gru_kernel<<<1, 1024>>>(lh, out);
    // 3) attention scores: 4096 warp-rows -> 512 blocks
    scores_kernel<<<512, 256>>>(enc, attn_slot);
    // 4) softmax (+ zero g_ctx)
    softmax_kernel<<<1, 1024>>>(attn_slot);
    // 5) context = attn @ enc
    {
        dim3 g(H / 128, S / 128);
        context_kernel<<<g, 128>>>(enc, attn_slot);
    }
    // 6) logits: warp per vocab row, 8 rows/block
    logits_kernel<<<(V + 7) / 8, 256>>>(out_w, out_b, out);
    // 7) log_softmax + context finalize
    lsm_kernel<<<1, 1024>>>(out);
}